// round 2
// baseline (speedup 1.0000x reference)
#include <cuda_runtime.h>
#include <math.h>

// Problem constants
#define Bz 64
#define Oz 32
#define Iz 2048
#define Dz 16   // DOUT == DIN == 16

// ---------------- scratch (static device globals; no allocation) ----------------
__device__ float g_uhat[(size_t)Bz * Oz * Dz * Iz];   // 256 MiB, layout [b][o][d][i]
__device__ float g_d[(size_t)Bz * Oz * Iz];           // distances d[b][o][i]
__device__ float g_c[(size_t)Bz * Oz * Iz];           // routing coeffs (scratch for iter 1)
__device__ float g_v[Bz * Oz * Dz];                   // v_j scratch
__device__ float g_partial[Bz * Oz];                  // per-CTA partial sums of d
__device__ float g_t;                                 // gamma-routing scalar t

// =======================================================================
// K1: u_hat[b,o,d,i] = clip( sum_k W[o,i,d,k] * u[b,i,k] )
// Grid: (I/32, O). Block: 256. Lane = i within 32-block (coalesced loads/stores),
// each thread handles 8 batches in 2 passes of 4 (W smem value reused 4x -> 1 LDS / 4 FFMA).
// =======================================================================
__global__ __launch_bounds__(256, 1) void k_uhat(const float* __restrict__ u,
                                                 const float* __restrict__ W)
{
    __shared__ float Wsm[32 * 257];   // row stride 257 -> conflict-free lane-per-i reads

    const int o  = blockIdx.y;
    const int i0 = blockIdx.x * 32;

    // Stage W[o, i0..i0+31, :, :] : contiguous 8192 floats
    const float* Wg = W + ((size_t)o * Iz + i0) * 256;
    for (int idx = threadIdx.x; idx < 8192; idx += 256) {
        int il = idx >> 8, j = idx & 255;
        Wsm[il * 257 + j] = Wg[idx];
    }
    __syncthreads();

    const int il = threadIdx.x & 31;
    const int bg = threadIdx.x >> 5;        // 0..7
    const int i  = i0 + il;

    for (int p = 0; p < 2; p++) {
        const int bbase = p * 32 + bg * 4;
        float ur[4][16];
        float acc[4][16];

        // load u for 4 batches (coalesced float4)
        #pragma unroll
        for (int jj = 0; jj < 4; jj++) {
            const float4* up = (const float4*)(u + ((size_t)(bbase + jj) * Iz + i) * 16);
            #pragma unroll
            for (int k4 = 0; k4 < 4; k4++) {
                float4 t = up[k4];
                ur[jj][k4 * 4 + 0] = t.x;
                ur[jj][k4 * 4 + 1] = t.y;
                ur[jj][k4 * 4 + 2] = t.z;
                ur[jj][k4 * 4 + 3] = t.w;
            }
        }

        #pragma unroll
        for (int d = 0; d < 16; d++) {
            float a0 = 0.f, a1 = 0.f, a2 = 0.f, a3 = 0.f;
            #pragma unroll
            for (int k = 0; k < 16; k++) {
                float w = Wsm[il * 257 + d * 16 + k];
                a0 += w * ur[0][k];
                a1 += w * ur[1][k];
                a2 += w * ur[2][k];
                a3 += w * ur[3][k];
            }
            acc[0][d] = a0; acc[1][d] = a1; acc[2][d] = a2; acc[3][d] = a3;
        }

        #pragma unroll
        for (int jj = 0; jj < 4; jj++) {
            float n2h = 0.f, n2u = 0.f;
            #pragma unroll
            for (int d = 0; d < 16; d++) n2h += acc[jj][d] * acc[jj][d];
            #pragma unroll
            for (int k = 0; k < 16; k++) n2u += ur[jj][k] * ur[jj][k];
            float nh = sqrtf(n2h);
            float nu = sqrtf(n2u);
            float sc = fminf(nh, nu) / (nh + 1e-12f);

            const int b = bbase + jj;
            float* dst = g_uhat + (size_t)(b * Oz + o) * Dz * Iz + i;
            #pragma unroll
            for (int d = 0; d < 16; d++) dst[(size_t)d * Iz] = acc[jj][d] * sc;
        }
    }
}

// =======================================================================
// k_s: s[b,o,:] = sum_i c[b,o,i] * u_hat[b,o,:,i] + bias ; v = squash(s)
// mode 0: c = 1/O (uniform, iter 0); mode 1: c = g_c; mode 2: c = cext.
// vext == nullptr -> write to g_v, else write to vext (final output).
// Grid: (O, B). Block: 256.
// =======================================================================
__global__ void k_s(const float* __restrict__ cext, int mode,
                    const float* __restrict__ bias, float* __restrict__ vext)
{
    const int o = blockIdx.x;
    const int b = blockIdx.y;
    const size_t base = (size_t)(b * Oz + o);
    const float* uh = g_uhat + base * Dz * Iz;

    float acc[16];
    #pragma unroll
    for (int d = 0; d < 16; d++) acc[d] = 0.f;

    if (mode == 0) {
        for (int i = threadIdx.x; i < Iz; i += 256) {
            #pragma unroll
            for (int d = 0; d < 16; d++) acc[d] += uh[(size_t)d * Iz + i];
        }
    } else {
        const float* cp = (mode == 1 ? g_c : cext) + base * Iz;
        for (int i = threadIdx.x; i < Iz; i += 256) {
            float cc = cp[i];
            #pragma unroll
            for (int d = 0; d < 16; d++) acc[d] += cc * uh[(size_t)d * Iz + i];
        }
    }

    // warp reduce
    #pragma unroll
    for (int d = 0; d < 16; d++) {
        #pragma unroll
        for (int off = 16; off > 0; off >>= 1)
            acc[d] += __shfl_down_sync(0xffffffffu, acc[d], off);
    }

    __shared__ float red[8][16];
    const int lane = threadIdx.x & 31;
    const int wid  = threadIdx.x >> 5;
    if (lane == 0) {
        #pragma unroll
        for (int d = 0; d < 16; d++) red[wid][d] = acc[d];
    }
    __syncthreads();

    if (threadIdx.x < 16) {
        const int d = threadIdx.x;
        float tot = 0.f;
        #pragma unroll
        for (int w = 0; w < 8; w++) tot += red[w][d];
        if (mode == 0) tot *= (1.0f / 32.0f);
        float s = tot + bias[o * Dz + d];

        // squash needs ||s||^2 across the 16 lanes
        float n2 = s * s;
        #pragma unroll
        for (int off = 8; off > 0; off >>= 1)
            n2 += __shfl_xor_sync(0x0000ffffu, n2, off);

        float vv = s * (n2 / ((1.0f + n2) * sqrtf(n2 + 1e-12f)));
        float* vo = vext ? vext : g_v;
        vo[(b * Oz + o) * Dz + d] = vv;
    }
}

// =======================================================================
// k_d: d[b,o,i] = || g_v[b,o,:] - u_hat[b,o,:,i] || ; per-CTA sum -> g_partial
// Grid: (O, B). Block: 256. Deterministic (fixed reduction order).
// =======================================================================
__global__ void k_d()
{
    const int o = blockIdx.x;
    const int b = blockIdx.y;
    const size_t base = (size_t)(b * Oz + o);
    const float* uh = g_uhat + base * Dz * Iz;

    float vr[16];
    #pragma unroll
    for (int d = 0; d < 16; d++) vr[d] = g_v[(b * Oz + o) * Dz + d];

    float* dp = g_d + base * Iz;
    float lsum = 0.f;
    for (int i = threadIdx.x; i < Iz; i += 256) {
        float s2 = 0.f;
        #pragma unroll
        for (int d = 0; d < 16; d++) {
            float df = vr[d] - uh[(size_t)d * Iz + i];
            s2 += df * df;
        }
        float dd = sqrtf(s2);
        dp[i] = dd;
        lsum += dd;
    }

    #pragma unroll
    for (int off = 16; off > 0; off >>= 1)
        lsum += __shfl_down_sync(0xffffffffu, lsum, off);

    __shared__ float red[8];
    const int lane = threadIdx.x & 31;
    const int wid  = threadIdx.x >> 5;
    if (lane == 0) red[wid] = lsum;
    __syncthreads();
    if (threadIdx.x == 0) {
        float t = 0.f;
        #pragma unroll
        for (int w = 0; w < 8; w++) t += red[w];
        g_partial[base] = t;
    }
}

// =======================================================================
// k_t: t = t_const / (d_p - d_o + 1e-12), d_p = 0.5*d_o, d_o = mean(d)
// Single block, deterministic fixed-order sum of 2048 partials.
// =======================================================================
__global__ void k_t()
{
    float s = 0.f;
    for (int idx = threadIdx.x; idx < Bz * Oz; idx += 256) s += g_partial[idx];

    #pragma unroll
    for (int off = 16; off > 0; off >>= 1)
        s += __shfl_down_sync(0xffffffffu, s, off);

    __shared__ float red[8];
    const int lane = threadIdx.x & 31;
    const int wid  = threadIdx.x >> 5;
    if (lane == 0) red[wid] = s;
    __syncthreads();
    if (threadIdx.x == 0) {
        float tot = 0.f;
        #pragma unroll
        for (int w = 0; w < 8; w++) tot += red[w];
        float mean = tot / (float)((size_t)Bz * Oz * Iz);
        // t_const = log(0.9*(O-1)) - log(0.1) = ln(279)
        const float t_const = 5.6312118f;
        g_t = t_const / (1e-12f - 0.5f * mean);
    }
}

// =======================================================================
// k_c: c[b,o,i] = softmax over o of (t * d[b,o,i]).
// cout == nullptr -> write g_c, else write cout (final output region).
// One thread per (b,i): 131072 threads -> 512 blocks x 256.
// =======================================================================
__global__ void k_c(float* __restrict__ cout)
{
    const int idx = blockIdx.x * 256 + threadIdx.x;
    const int b = idx >> 11;          // / 2048
    const int i = idx & (Iz - 1);
    const float t = g_t;

    float vals[32];
    float mx = -1e30f;
    #pragma unroll
    for (int o = 0; o < 32; o++) {
        float x = t * g_d[(size_t)(b * Oz + o) * Iz + i];
        vals[o] = x;
        mx = fmaxf(mx, x);
    }
    float ssum = 0.f;
    #pragma unroll
    for (int o = 0; o < 32; o++) {
        float e = expf(vals[o] - mx);
        vals[o] = e;
        ssum += e;
    }
    float inv = 1.0f / ssum;
    float* dst = cout ? cout : g_c;
    #pragma unroll
    for (int o = 0; o < 32; o++)
        dst[(size_t)(b * Oz + o) * Iz + i] = vals[o] * inv;
}

// =======================================================================
extern "C" void kernel_launch(void* const* d_in, const int* in_sizes, int n_in,
                              void* d_out, int out_size)
{
    const float* u    = (const float*)d_in[0];   // [64, 2048, 16]
    const float* W    = (const float*)d_in[1];   // [1, 32, 2048, 16, 16]
    const float* bias = (const float*)d_in[2];   // [1, 32, 16]

    float* out        = (float*)d_out;
    float* vout_final = out;                     // [64,32,16]
    float* cout_final = out + Bz * Oz * Dz;      // [64,32,2048,1]

    dim3 gUH(Iz / 32, Oz);
    dim3 gBO(Oz, Bz);

    k_uhat<<<gUH, 256>>>(u, W);

    // iteration 0: c uniform
    k_s<<<gBO, 256>>>(nullptr, 0, bias, nullptr);      // v0 -> g_v
    k_d<<<gBO, 256>>>();                               // d0 + partial sums
    k_t<<<1, 256>>>();                                 // t0

    // iteration 1
    k_c<<<(Bz * Iz) / 256, 256>>>(nullptr);            // c1 -> g_c
    k_s<<<gBO, 256>>>(nullptr, 1, bias, nullptr);      // v1 -> g_v
    k_d<<<gBO, 256>>>();                               // d1 + partial sums
    k_t<<<1, 256>>>();                                 // t1

    // iteration 2 (final): c2 and v2 go straight to d_out
    k_c<<<(Bz * Iz) / 256, 256>>>(cout_final);         // c2 -> out
    k_s<<<gBO, 256>>>(cout_final, 2, bias, vout_final);// v2 -> out
}

// round 3
// speedup vs baseline: 1.1224x; 1.1224x over previous
#include <cuda_runtime.h>
#include <math.h>

// Problem constants
#define Bz 64
#define Oz 32
#define Iz 2048
#define Dz 16   // DOUT == DIN == 16

// ---------------- scratch (static device globals; no allocation) ----------------
__device__ float g_uhat[(size_t)Bz * Oz * Dz * Iz];   // 256 MiB, layout [b][o][d][i]
__device__ float g_d[(size_t)Bz * Oz * Iz];           // distances d[b][o][i]
__device__ float g_c[(size_t)Bz * Oz * Iz];           // routing coeffs (iter-1 scratch)
__device__ float g_partial[Bz * Oz];                  // per-CTA partial sums of d

// =======================================================================
// K1: u_hat[b,o,d,i] = clip( sum_k W[o,i,d,k] * u[b,i,k] )
// Grid: (I/32, O). Block: 256. Lane = i within 32-block (coalesced),
// each thread handles 8 batches in 2 passes of 4.
// =======================================================================
__global__ __launch_bounds__(256, 1) void k_uhat(const float* __restrict__ u,
                                                 const float* __restrict__ W)
{
    __shared__ float Wsm[32 * 257];   // row stride 257 -> conflict-free lane-per-i reads

    const int o  = blockIdx.y;
    const int i0 = blockIdx.x * 32;

    // Stage W[o, i0..i0+31, :, :] : contiguous 8192 floats
    const float* Wg = W + ((size_t)o * Iz + i0) * 256;
    for (int idx = threadIdx.x; idx < 8192; idx += 256) {
        int il = idx >> 8, j = idx & 255;
        Wsm[il * 257 + j] = Wg[idx];
    }
    __syncthreads();

    const int il = threadIdx.x & 31;
    const int bg = threadIdx.x >> 5;        // 0..7
    const int i  = i0 + il;

    for (int p = 0; p < 2; p++) {
        const int bbase = p * 32 + bg * 4;
        float ur[4][16];
        float acc[4][16];

        #pragma unroll
        for (int jj = 0; jj < 4; jj++) {
            const float4* up = (const float4*)(u + ((size_t)(bbase + jj) * Iz + i) * 16);
            #pragma unroll
            for (int k4 = 0; k4 < 4; k4++) {
                float4 t = up[k4];
                ur[jj][k4 * 4 + 0] = t.x;
                ur[jj][k4 * 4 + 1] = t.y;
                ur[jj][k4 * 4 + 2] = t.z;
                ur[jj][k4 * 4 + 3] = t.w;
            }
        }

        #pragma unroll
        for (int d = 0; d < 16; d++) {
            float a0 = 0.f, a1 = 0.f, a2 = 0.f, a3 = 0.f;
            #pragma unroll
            for (int k = 0; k < 16; k++) {
                float w = Wsm[il * 257 + d * 16 + k];
                a0 += w * ur[0][k];
                a1 += w * ur[1][k];
                a2 += w * ur[2][k];
                a3 += w * ur[3][k];
            }
            acc[0][d] = a0; acc[1][d] = a1; acc[2][d] = a2; acc[3][d] = a3;
        }

        #pragma unroll
        for (int jj = 0; jj < 4; jj++) {
            float n2h = 0.f, n2u = 0.f;
            #pragma unroll
            for (int d = 0; d < 16; d++) n2h += acc[jj][d] * acc[jj][d];
            #pragma unroll
            for (int k = 0; k < 16; k++) n2u += ur[jj][k] * ur[jj][k];
            float nh = sqrtf(n2h);
            float nu = sqrtf(n2u);
            float sc = fminf(nh, nu) / (nh + 1e-12f);

            const int b = bbase + jj;
            float* dst = g_uhat + (size_t)(b * Oz + o) * Dz * Iz + i;
            #pragma unroll
            for (int d = 0; d < 16; d++) dst[(size_t)d * Iz] = acc[jj][d] * sc;
        }
    }
}

// =======================================================================
// k_sd: FUSED s/v computation + distance pass. One read of u_hat.
//   s[b,o,:] = sum_i c*u_hat + bias ; v = squash(s)
//   d[b,o,i] = ||v - u_hat[b,o,:,i]|| ; per-CTA sum -> g_partial
// mode 0: c = 1/O uniform ; mode 1: c = g_c.
// Grid: (O, B). Block: 512 (each thread holds 4 i's x 16 d in registers).
// =======================================================================
__global__ __launch_bounds__(512, 1) void k_sd(int mode, const float* __restrict__ bias)
{
    const int o = blockIdx.x;
    const int b = blockIdx.y;
    const size_t base = (size_t)(b * Oz + o);
    const float* uh = g_uhat + base * Dz * Iz;

    float uhr[4][16];
    float acc[16];
    #pragma unroll
    for (int d = 0; d < 16; d++) acc[d] = 0.f;

    const float* cp = g_c + base * Iz;

    #pragma unroll
    for (int jj = 0; jj < 4; jj++) {
        const int i = threadIdx.x + jj * 512;
        const float cc = (mode == 0) ? (1.0f / 32.0f) : cp[i];
        #pragma unroll
        for (int d = 0; d < 16; d++) {
            float x = uh[(size_t)d * Iz + i];
            uhr[jj][d] = x;
            acc[d] += cc * x;
        }
    }

    // ---- reduce acc across 512 threads ----
    #pragma unroll
    for (int d = 0; d < 16; d++) {
        #pragma unroll
        for (int off = 16; off > 0; off >>= 1)
            acc[d] += __shfl_down_sync(0xffffffffu, acc[d], off);
    }

    __shared__ float red[16][16];
    __shared__ float vsm[16];
    const int lane = threadIdx.x & 31;
    const int wid  = threadIdx.x >> 5;        // 0..15
    if (lane == 0) {
        #pragma unroll
        for (int d = 0; d < 16; d++) red[wid][d] = acc[d];
    }
    __syncthreads();

    if (threadIdx.x < 16) {
        const int d = threadIdx.x;
        float tot = 0.f;
        #pragma unroll
        for (int w = 0; w < 16; w++) tot += red[w][d];
        float s = tot + bias[o * Dz + d];

        // squash: needs ||s||^2 across the 16 lanes
        float n2 = s * s;
        #pragma unroll
        for (int off = 8; off > 0; off >>= 1)
            n2 += __shfl_xor_sync(0x0000ffffu, n2, off);

        vsm[d] = s * (n2 / ((1.0f + n2) * sqrtf(n2 + 1e-12f)));
    }
    __syncthreads();

    // ---- distance pass from registers ----
    float vr[16];
    #pragma unroll
    for (int d = 0; d < 16; d++) vr[d] = vsm[d];

    float* dp = g_d + base * Iz;
    float lsum = 0.f;
    #pragma unroll
    for (int jj = 0; jj < 4; jj++) {
        const int i = threadIdx.x + jj * 512;
        float s2 = 0.f;
        #pragma unroll
        for (int d = 0; d < 16; d++) {
            float df = vr[d] - uhr[jj][d];
            s2 += df * df;
        }
        float dd = sqrtf(s2);
        dp[i] = dd;
        lsum += dd;
    }

    #pragma unroll
    for (int off = 16; off > 0; off >>= 1)
        lsum += __shfl_down_sync(0xffffffffu, lsum, off);

    __shared__ float red1[16];
    if (lane == 0) red1[wid] = lsum;
    __syncthreads();
    if (threadIdx.x == 0) {
        float t = 0.f;
        #pragma unroll
        for (int w = 0; w < 16; w++) t += red1[w];
        g_partial[base] = t;
    }
}

// =======================================================================
// k_c: computes t from g_partial (deterministic fixed-order, identical in
// every block), then c[b,o,i] = softmax over o of (t * d[b,o,i]).
// cout == nullptr -> write g_c, else write cout (final output region).
// One thread per (b,i): 512 blocks x 256 threads.
// =======================================================================
__global__ __launch_bounds__(256, 1) void k_c(float* __restrict__ cout)
{
    // ---- prologue: mean(d) -> t (identical fixed-order sum in every block) ----
    __shared__ float psum[256];
    __shared__ float tsh;
    {
        float s = 0.f;
        const int j0 = threadIdx.x * 8;
        #pragma unroll
        for (int j = 0; j < 8; j++) s += g_partial[j0 + j];
        psum[threadIdx.x] = s;
    }
    __syncthreads();
    if (threadIdx.x == 0) {
        float tot = 0.f;
        for (int w = 0; w < 256; w++) tot += psum[w];
        float mean = tot / (float)((size_t)Bz * Oz * Iz);
        // t_const = log(0.9*(O-1)) - log(0.1) = ln(279)
        const float t_const = 5.6312118f;
        tsh = t_const / (1e-12f - 0.5f * mean);
    }
    __syncthreads();
    const float t = tsh;

    const int idx = blockIdx.x * 256 + threadIdx.x;
    const int b = idx >> 11;          // / 2048
    const int i = idx & (Iz - 1);

    float vals[32];
    float mx = -1e30f;
    #pragma unroll
    for (int o = 0; o < 32; o++) {
        float x = t * g_d[(size_t)(b * Oz + o) * Iz + i];
        vals[o] = x;
        mx = fmaxf(mx, x);
    }
    float ssum = 0.f;
    #pragma unroll
    for (int o = 0; o < 32; o++) {
        float e = expf(vals[o] - mx);
        vals[o] = e;
        ssum += e;
    }
    float inv = 1.0f / ssum;
    float* dst = cout ? cout : g_c;
    #pragma unroll
    for (int o = 0; o < 32; o++)
        dst[(size_t)(b * Oz + o) * Iz + i] = vals[o] * inv;
}

// =======================================================================
// k_s_final: final s/v with c read from the output buffer; writes v to out.
// Grid: (O, B). Block: 256.
// =======================================================================
__global__ __launch_bounds__(256, 1) void k_s_final(const float* __restrict__ cext,
                                                    const float* __restrict__ bias,
                                                    float* __restrict__ vext)
{
    const int o = blockIdx.x;
    const int b = blockIdx.y;
    const size_t base = (size_t)(b * Oz + o);
    const float* uh = g_uhat + base * Dz * Iz;
    const float* cp = cext + base * Iz;

    float acc[16];
    #pragma unroll
    for (int d = 0; d < 16; d++) acc[d] = 0.f;

    for (int i = threadIdx.x; i < Iz; i += 256) {
        float cc = cp[i];
        #pragma unroll
        for (int d = 0; d < 16; d++) acc[d] += cc * uh[(size_t)d * Iz + i];
    }

    #pragma unroll
    for (int d = 0; d < 16; d++) {
        #pragma unroll
        for (int off = 16; off > 0; off >>= 1)
            acc[d] += __shfl_down_sync(0xffffffffu, acc[d], off);
    }

    __shared__ float red[8][16];
    const int lane = threadIdx.x & 31;
    const int wid  = threadIdx.x >> 5;
    if (lane == 0) {
        #pragma unroll
        for (int d = 0; d < 16; d++) red[wid][d] = acc[d];
    }
    __syncthreads();

    if (threadIdx.x < 16) {
        const int d = threadIdx.x;
        float tot = 0.f;
        #pragma unroll
        for (int w = 0; w < 8; w++) tot += red[w][d];
        float s = tot + bias[o * Dz + d];

        float n2 = s * s;
        #pragma unroll
        for (int off = 8; off > 0; off >>= 1)
            n2 += __shfl_xor_sync(0x0000ffffu, n2, off);

        vext[(b * Oz + o) * Dz + d] = s * (n2 / ((1.0f + n2) * sqrtf(n2 + 1e-12f)));
    }
}

// =======================================================================
extern "C" void kernel_launch(void* const* d_in, const int* in_sizes, int n_in,
                              void* d_out, int out_size)
{
    const float* u    = (const float*)d_in[0];   // [64, 2048, 16]
    const float* W    = (const float*)d_in[1];   // [1, 32, 2048, 16, 16]
    const float* bias = (const float*)d_in[2];   // [1, 32, 16]

    float* out        = (float*)d_out;
    float* vout_final = out;                     // [64,32,16]
    float* cout_final = out + Bz * Oz * Dz;      // [64,32,2048,1]

    dim3 gUH(Iz / 32, Oz);
    dim3 gBO(Oz, Bz);

    k_uhat<<<gUH, 256>>>(u, W);

    // iteration 0: c uniform; fused s/v + d
    k_sd<<<gBO, 512>>>(0, bias);

    // iteration 1
    k_c<<<(Bz * Iz) / 256, 256>>>(nullptr);      // t + softmax -> g_c
    k_sd<<<gBO, 512>>>(1, bias);

    // iteration 2 (final): c2 and v2 go straight to d_out
    k_c<<<(Bz * Iz) / 256, 256>>>(cout_final);   // t + softmax -> out
    k_s_final<<<gBO, 256>>>(cout_final, bias, vout_final);
}